// round 14
// baseline (speedup 1.0000x reference)
#include <cuda_runtime.h>
#include <cuda_bf16.h>
#include <cstdint>

#define NPTS   8192
#define KNBR   64
#define CIN    64
#define H1DIM  64
#define H2DIM  128
#define ODIM   256
#define R2     0.015625f   // 0.125^2 exactly
#define CAP    192         // per-target hit cap (mean ~60 in-radius)
#define GRID   8           // 8x8x8 cells, width 0.125 == R
#define NCELLS (GRID * GRID * GRID)
#define MAXC   768         // 27-cell candidate cap (mean 432, +16 sigma)

#define BSTRIDE 72         // halves per row of B planes (144B, 16B-aligned, conflict-free)

typedef unsigned long long ull;

// ---- scratch (device globals; no allocation allowed) ----------------------
__device__ int    g_nbr[NPTS * KNBR];
__device__ float  g_G  [NPTS * CIN];        // x @ W1[:64] + b1
__device__ float  g_AGG[NPTS * H2DIM];      // max-aggregated h2
__device__ float2 g_Wgd[H2DIM * ODIM];      // Wg duplicated (w,w)
__device__ float4 g_pos4[NPTS];             // (x, y, z, |p|^2)
__device__ uint4  g_AF4[64 * 32];           // pre-baked W2^T mma A-fragments
                                            // frag = ((w*2+mt)*4+kt)*2+plane, [frag][lane]
// spatial grid (cnt/fill zero at entry each call: zero-init at load, re-zeroed
// by scan_kernel after consuming -> graph-replay safe)
__device__ int    g_cell_cnt[NCELLS];
__device__ int    g_cell_start[NCELLS];
__device__ int    g_cell_end[NCELLS];
__device__ int    g_cell_fill[NCELLS];
__device__ float4 g_pos4s[NPTS];
__device__ int    g_ptid[NPTS];

__device__ __forceinline__ void fma2(ull& d, ull a, ull b) {
    asm("fma.rn.f32x2 %0, %1, %2, %0;" : "+l"(d) : "l"(a), "l"(b));
}
__device__ __forceinline__ int cell_of(float v) {
    int c = (int)(v * (float)GRID);
    return min(max(c, 0), GRID - 1);
}
// round-to-nearest-even fp32 -> bf16 (bits)  (prep-side; matches cvt.rn)
__device__ __forceinline__ unsigned bf16rn(float f) {
    unsigned u = __float_as_uint(f);
    return (u + 0x7FFFu + ((u >> 16) & 1u)) >> 16;
}
// hardware pack: bits[15:0] = bf16rn(a), bits[31:16] = bf16rn(b)
__device__ __forceinline__ uint32_t pack_bf16x2(float a, float b) {
    uint32_t r;
    asm("cvt.rn.bf16x2.f32 %0, %1, %2;" : "=r"(r) : "f"(b), "f"(a));
    return r;
}
__device__ __forceinline__ uint32_t smem_to_u32(const void* p) {
    uint32_t a;
    asm("{ .reg .u64 t; cvta.to.shared.u64 t, %1; cvt.u32.u64 %0, t; }" : "=r"(a) : "l"(p));
    return a;
}

// mma.sync m16n8k16 bf16, fp32 accum (baseline PTX; valid on compute_103)
#define MMA_BF16(acc, a, b0v, b1v) \
    asm volatile("mma.sync.aligned.m16n8k16.row.col.f32.bf16.bf16.f32 " \
        "{%0,%1,%2,%3}, {%4,%5,%6,%7}, {%8,%9}, {%0,%1,%2,%3};" \
        : "+f"((acc)[0]), "+f"((acc)[1]), "+f"((acc)[2]), "+f"((acc)[3]) \
        : "r"((a).x), "r"((a).y), "r"((a).z), "r"((a).w), "r"(b0v), "r"(b1v))

#define LDSM_X4(r0, r1, r2, r3, addr) \
    asm volatile("ldmatrix.sync.aligned.m8n8.x4.shared.b16 {%0,%1,%2,%3}, [%4];" \
        : "=r"(r0), "=r"(r1), "=r"(r2), "=r"(r3) : "r"(addr))

// ---------------------------------------------------------------------------
// Prep: Wg dup pairs; pos4 pack + cell histogram; bake W2^T A-fragments.
// ---------------------------------------------------------------------------
__global__ void prep_kernel(const float* __restrict__ W2, const float* __restrict__ Wg,
                            const float* __restrict__ pos, int n)
{
    int t = blockIdx.x * 256 + threadIdx.x;
    if (t < H2DIM * ODIM) {
        float w = Wg[t];
        g_Wgd[t] = make_float2(w, w);
    }
    if (t < n) {
        const float px = pos[3 * t + 0];
        const float py = pos[3 * t + 1];
        const float pz = pos[3 * t + 2];
        g_pos4[t] = make_float4(px, py, pz, px * px + py * py + pz * pz);
        const int c = (cell_of(pz) * GRID + cell_of(py)) * GRID + cell_of(px);
        atomicAdd(&g_cell_cnt[c], 1);      // cnt is zero at entry (see scan)
    }
    // A-fragment baking: a0=(r,k), a1=(r+8,k), a2=(r,k+8), a3=(r+8,k+8);
    // per-lane: row = base_m + lane/4, k = base_k + 2*(lane%4)+{0,1}
    int t4 = t - H2DIM * ODIM;
    if (t4 >= 0 && t4 < 64 * 32) {
        const int frag = t4 >> 5, lane = t4 & 31;
        const int plane = frag & 1;
        const int kt    = (frag >> 1) & 3;
        const int mt    = (frag >> 3) & 1;
        const int ww    = frag >> 4;
        const int r = 32 * ww + 16 * mt + (lane >> 2);
        const int k = 16 * kt + 2 * (lane & 3);
        uint32_t regs[4];
        #pragma unroll
        for (int j = 0; j < 4; j++) {
            const int rr = r + (j & 1) * 8;
            const int kk = k + (j >> 1) * 8;
            const float v0 = W2[(size_t)kk * H2DIM + rr];       // W2^T[rr][kk]
            const float v1 = W2[(size_t)(kk + 1) * H2DIM + rr];
            unsigned h0 = bf16rn(v0), h1 = bf16rn(v1);
            if (plane) {
                h0 = bf16rn(v0 - __uint_as_float(h0 << 16));
                h1 = bf16rn(v1 - __uint_as_float(h1 << 16));
            }
            regs[j] = h0 | (h1 << 16);
        }
        g_AF4[frag * 32 + lane] = make_uint4(regs[0], regs[1], regs[2], regs[3]);
    }
}

// ---------------------------------------------------------------------------
// Scan: counts -> start/end; then zero cnt/fill for the next replay.
// ---------------------------------------------------------------------------
__global__ void scan_kernel()
{
    __shared__ int buf[NCELLS];
    const int t = threadIdx.x;
    const int v = g_cell_cnt[t];
    buf[t] = v;
    __syncthreads();
    for (int o = 1; o < NCELLS; o <<= 1) {
        int u = (t >= o) ? buf[t - o] : 0;
        __syncthreads();
        buf[t] += u;
        __syncthreads();
    }
    g_cell_start[t] = buf[t] - v;   // exclusive prefix
    g_cell_end[t]   = buf[t];       // inclusive end
    g_cell_cnt[t]   = 0;            // reset for next graph replay
    g_cell_fill[t]  = 0;
}

__global__ void scatter_kernel(int n)
{
    int t = blockIdx.x * 256 + threadIdx.x;
    if (t >= n) return;
    const float4 p = g_pos4[t];
    const int c = (cell_of(p.z) * GRID + cell_of(p.y)) * GRID + cell_of(p.x);
    const int slot = g_cell_start[c] + atomicAdd(&g_cell_fill[c], 1);
    g_pos4s[slot] = p;
    g_ptid[slot]  = t;
}

// ---------------------------------------------------------------------------
// Cell-centric KNN: one block per cell. Stage the 27-cell candidate list to
// smem ONCE, then warp-per-target sweeps from smem (contiguous, LDS.128).
// Candidate set per target identical to the validated 27-cell coverage
// (cell width == R); selection logic unchanged (radius filter, (d2,idx) rank
// if > K, pad with self).
// ---------------------------------------------------------------------------
__global__ void __launch_bounds__(128) knn_kernel()
{
    __shared__ __align__(16) float4 cpos[MAXC];
    __shared__ int   cid [MAXC];
    __shared__ float cd2 [4][CAP];
    __shared__ int   cidx[4][CAP];
    __shared__ int   cnt[4];

    const int cell = blockIdx.x;
    const int tid  = threadIdx.x;
    const int wid  = tid >> 5;
    const int lane = tid & 31;

    const int t0 = g_cell_start[cell];
    const int t1 = g_cell_end[cell];
    const int ntgt = t1 - t0;
    if (ntgt == 0) return;

    const int cx = cell & 7, cy = (cell >> 3) & 7, cz = cell >> 6;
    const int zlo = max(cz - 1, 0), zhi = min(cz + 1, GRID - 1);
    const int ylo = max(cy - 1, 0), yhi = min(cy + 1, GRID - 1);
    const int xlo = max(cx - 1, 0), xhi = min(cx + 1, GRID - 1);

    // ---- stage candidates (all threads compute identical offsets) ----
    int off = 0;
    for (int z = zlo; z <= zhi; z++)
        for (int y = ylo; y <= yhi; y++) {
            const int c0 = (z * GRID + y) * GRID + xlo;
            const int c1 = (z * GRID + y) * GRID + xhi;
            const int s0 = g_cell_start[c0];
            int len = g_cell_end[c1] - s0;
            if (off + len > MAXC) len = MAXC - off;   // overflow guard (P~0)
            for (int k = tid; k < len; k += 128) {
                cpos[off + k] = g_pos4s[s0 + k];
                cid [off + k] = g_ptid[s0 + k];
            }
            off += len;
        }
    __syncthreads();
    const int M = off;

    // ---- warp-per-target sweep over the shared candidate list ----
    for (int tt = wid; tt < ntgt; tt += 4) {
        const int slot  = t0 + tt;
        const float4 q  = g_pos4s[slot];
        const int iorig = g_ptid[slot];

        if (lane == 0) cnt[wid] = 0;
        __syncwarp();

        for (int s = lane; s < M; s += 32) {
            const float4 p = cpos[s];
            const float dot = p.x * q.x + p.y * q.y + p.z * q.z;
            const float d2  = (q.w + p.w) - 2.0f * dot;   // same formula as reference
            if (d2 <= R2) {
                int sl = atomicAdd(&cnt[wid], 1);
                if (sl < CAP) { cd2[wid][sl] = d2; cidx[wid][sl] = cid[s]; }
            }
        }
        __syncwarp();

        int Mh = cnt[wid]; if (Mh > CAP) Mh = CAP;

        if (Mh <= KNBR) {
            for (int l = lane; l < KNBR; l += 32)
                g_nbr[iorig * KNBR + l] = (l < Mh) ? cidx[wid][l] : iorig;  // pad self
        } else {
            for (int m = lane; m < Mh; m += 32) {
                const float dm = cd2[wid][m];
                const int   im = cidx[wid][m];
                int rank = 0;
                for (int qq = 0; qq < Mh; qq++) {
                    const float dq = cd2[wid][qq];
                    rank += (dq < dm) || (dq == dm && cidx[wid][qq] < im);
                }
                if (rank < KNBR) g_nbr[iorig * KNBR + rank] = cidx[wid][m];
            }
        }
        __syncwarp();   // cnt reused next iteration
    }
}

// ---------------------------------------------------------------------------
// G precompute: G = x @ W1[0:64,:] + b1
// ---------------------------------------------------------------------------
__global__ void __launch_bounds__(128) g_kernel(
    const float* __restrict__ x, const float* __restrict__ W1,
    const float* __restrict__ b1, int n)
{
    __shared__ __align__(16) float xs[8 * 64];
    const int tid = threadIdx.x;
    const int i0  = blockIdx.x * 8;

    for (int idx = tid; idx < 512; idx += 128) {
        int p = idx >> 6, d = idx & 63;
        xs[idx] = (i0 + p < n) ? x[(size_t)(i0 + p) * 64 + d] : 0.0f;
    }
    __syncthreads();

    const int p  = tid >> 4;
    const int c4 = (tid & 15) * 4;
    if (i0 + p >= n) return;

    float4 acc = *(const float4*)&b1[c4];
    const float* xr = &xs[p * 64];
    #pragma unroll 8
    for (int d = 0; d < 64; d++) {
        const float xv = xr[d];
        float4 w = *(const float4*)&W1[d * 64 + c4];
        acc.x = fmaf(xv, w.x, acc.x);
        acc.y = fmaf(xv, w.y, acc.y);
        acc.z = fmaf(xv, w.z, acc.z);
        acc.w = fmaf(xv, w.w, acc.w);
    }
    *(float4*)&g_G[(size_t)(i0 + p) * 64 + c4] = acc;
}

// ---------------------------------------------------------------------------
// Main edge kernel: one block per point, 128 threads.  (UNCHANGED — protect
// the HMMA win.)
// ---------------------------------------------------------------------------
__global__ void __launch_bounds__(128) compute_kernel(
    const float* __restrict__ pos, const float* __restrict__ W1,
    const float* __restrict__ b2, int n)
{
    __shared__ __align__(16) unsigned short BHIs[KNBR * BSTRIDE];
    __shared__ __align__(16) unsigned short BLOs[KNBR * BSTRIDE];
    __shared__ int   nbr_s[KNBR];
    __shared__ float relx[KNBR], rely[KNBR], relz[KNBR];
    __shared__ float red[H2DIM];

    const int i    = blockIdx.x;
    const int tid  = threadIdx.x;
    const int wid  = tid >> 5;
    const int lane = tid & 31;
    if (i >= n) return;

    if (tid < KNBR) {
        const int j = g_nbr[i * KNBR + tid];
        nbr_s[tid] = j;
        relx[tid] = pos[3 * j + 0] - pos[3 * i + 0];
        rely[tid] = pos[3 * j + 1] - pos[3 * i + 1];
        relz[tid] = pos[3 * j + 2] - pos[3 * i + 2];
    }
    __syncthreads();

    // ---- Phase A: fp32 h1 -> bf16 hi/lo planes, [nbr][d] stride 72 halves ----
    {
        const int nk0 = tid & 7;
        const int c4  = (tid >> 3) * 4;

        float4 g4[8];
        #pragma unroll
        for (int it = 0; it < 8; it++)
            g4[it] = *(const float4*)&g_G[(size_t)nbr_s[nk0 + it * 8] * 64 + c4];

        const float4 wx = *(const float4*)&W1[64 * 64 + c4];
        const float4 wy = *(const float4*)&W1[65 * 64 + c4];
        const float4 wz = *(const float4*)&W1[66 * 64 + c4];

        #pragma unroll
        for (int it = 0; it < 8; it++) {
            const int nk = nk0 + it * 8;
            const float rx = relx[nk], ry = rely[nk], rz = relz[nk];
            float h0 = fmaxf(fmaf(rx, wx.x, fmaf(ry, wy.x, fmaf(rz, wz.x, g4[it].x))), 0.0f);
            float h1 = fmaxf(fmaf(rx, wx.y, fmaf(ry, wy.y, fmaf(rz, wz.y, g4[it].y))), 0.0f);
            float h2 = fmaxf(fmaf(rx, wx.z, fmaf(ry, wy.z, fmaf(rz, wz.z, g4[it].z))), 0.0f);
            float h3 = fmaxf(fmaf(rx, wx.w, fmaf(ry, wy.w, fmaf(rz, wz.w, g4[it].w))), 0.0f);

            const uint32_t p01 = pack_bf16x2(h0, h1);
            const uint32_t p23 = pack_bf16x2(h2, h3);
            const float f0 = __uint_as_float(p01 << 16);
            const float f1 = __uint_as_float(p01 & 0xFFFF0000u);
            const float f2 = __uint_as_float(p23 << 16);
            const float f3 = __uint_as_float(p23 & 0xFFFF0000u);
            const uint32_t q01 = pack_bf16x2(h0 - f0, h1 - f1);
            const uint32_t q23 = pack_bf16x2(h2 - f2, h3 - f3);

            const ull hiw = (ull)p01 | ((ull)p23 << 32);
            const ull low = (ull)q01 | ((ull)q23 << 32);
            *(ull*)&BHIs[nk * BSTRIDE + c4] = hiw;
            *(ull*)&BLOs[nk * BSTRIDE + c4] = low;
        }
    }
    __syncthreads();

    // ---- Phase B: mma.sync layer 2 + max-agg ----
    {
        const uint32_t bhi_base = smem_to_u32(BHIs);
        const uint32_t blo_base = smem_to_u32(BLOs);
        const int g  = lane >> 3;      // ldmatrix lane group 0..3
        const int gr = lane & 7;

        float mx[2][2] = {{-1e30f, -1e30f}, {-1e30f, -1e30f}};   // [mt][rowhalf]

        #pragma unroll
        for (int nh = 0; nh < 2; nh++) {
            float acc[2][4][4];
            #pragma unroll
            for (int mt = 0; mt < 2; mt++)
                #pragma unroll
                for (int nt = 0; nt < 4; nt++)
                    #pragma unroll
                    for (int e = 0; e < 4; e++) acc[mt][nt][e] = 0.0f;

            #pragma unroll
            for (int kt = 0; kt < 4; kt++) {
                // A fragments (pre-baked, coalesced LDG.128, L1-hot)
                uint4 ah[2], al[2];
                ah[0] = g_AF4[(((wid * 2 + 0) * 4 + kt) * 2 + 0) * 32 + lane];
                ah[1] = g_AF4[(((wid * 2 + 1) * 4 + kt) * 2 + 0) * 32 + lane];
                al[0] = g_AF4[(((wid * 2 + 0) * 4 + kt) * 2 + 1) * 32 + lane];
                al[1] = g_AF4[(((wid * 2 + 1) * 4 + kt) * 2 + 1) * 32 + lane];

                // B fragments via plain ldmatrix.x4
                uint32_t bh[4][2], bl[4][2];
                #pragma unroll
                for (int ntp = 0; ntp < 2; ntp++) {
                    const int row = nh * 32 + ntp * 16 + (g >> 1) * 8 + gr;
                    const uint32_t off = (uint32_t)(row * (BSTRIDE * 2) + (kt * 16 + (g & 1) * 8) * 2);
                    uint32_t r0, r1, r2, r3;
                    LDSM_X4(r0, r1, r2, r3, bhi_base + off);
                    bh[2 * ntp][0] = r0; bh[2 * ntp][1] = r1;
                    bh[2 * ntp + 1][0] = r2; bh[2 * ntp + 1][1] = r3;
                    LDSM_X4(r0, r1, r2, r3, blo_base + off);
                    bl[2 * ntp][0] = r0; bl[2 * ntp][1] = r1;
                    bl[2 * ntp + 1][0] = r2; bl[2 * ntp + 1][1] = r3;
                }

                #pragma unroll
                for (int mt = 0; mt < 2; mt++)
                    #pragma unroll
                    for (int nt = 0; nt < 4; nt++) {
                        MMA_BF16(acc[mt][nt], ah[mt], bh[nt][0], bh[nt][1]);
                        MMA_BF16(acc[mt][nt], ah[mt], bl[nt][0], bl[nt][1]);
                        MMA_BF16(acc[mt][nt], al[mt], bh[nt][0], bh[nt][1]);
                    }
            }

            // fold this n-half into running maxes
            #pragma unroll
            for (int mt = 0; mt < 2; mt++)
                #pragma unroll
                for (int nt = 0; nt < 4; nt++) {
                    mx[mt][0] = fmaxf(mx[mt][0], fmaxf(acc[mt][nt][0], acc[mt][nt][1]));
                    mx[mt][1] = fmaxf(mx[mt][1], fmaxf(acc[mt][nt][2], acc[mt][nt][3]));
                }
        }

        // quad reduction: lanes sharing l/4 hold the same rows
        #pragma unroll
        for (int mt = 0; mt < 2; mt++)
            #pragma unroll
            for (int h = 0; h < 2; h++) {
                float v = mx[mt][h];
                v = fmaxf(v, __shfl_xor_sync(0xffffffffu, v, 1));
                v = fmaxf(v, __shfl_xor_sync(0xffffffffu, v, 2));
                mx[mt][h] = v;
            }
        if ((lane & 3) == 0) {
            const int q = lane >> 2;
            red[32 * wid + q]      = mx[0][0];
            red[32 * wid + 8 + q]  = mx[0][1];
            red[32 * wid + 16 + q] = mx[1][0];
            red[32 * wid + 24 + q] = mx[1][1];
        }
    }
    __syncthreads();

    // relu(max + b2) == max relu(z + b2)  (max monotone)
    g_AGG[(size_t)i * H2DIM + tid] = fmaxf(red[tid] + b2[tid], 0.0f);
}

// ---------------------------------------------------------------------------
// Global layer GEMM: out = relu(AGG @ Wg + bg), packed f32x2.
// ---------------------------------------------------------------------------
__global__ void __launch_bounds__(256) gemm_kernel(
    const float* __restrict__ bg, float* __restrict__ out, int n)
{
    __shared__ __align__(16) float As[H2DIM * 36];
    const int tid = threadIdx.x;
    const int i0  = blockIdx.x * 32;

    for (int idx = tid; idx < 32 * H2DIM; idx += 256) {
        const int r = idx >> 7, d = idx & 127;
        const int row = (i0 + r < n) ? (i0 + r) : (n - 1);
        As[d * 36 + r] = g_AGG[(size_t)row * H2DIM + d];
    }
    __syncthreads();

    const int c = tid;
    ull acc[16];
    #pragma unroll
    for (int p = 0; p < 16; p++) acc[p] = 0ull;

    const ull* wp = reinterpret_cast<const ull*>(g_Wgd) + c;
    #pragma unroll 2
    for (int d = 0; d < H2DIM; d++) {
        const ull wd = *wp; wp += ODIM;
        const float* ar = &As[d * 36];
        #pragma unroll
        for (int p = 0; p < 8; p++) {
            const ulonglong2 av = *reinterpret_cast<const ulonglong2*>(ar + 4 * p);
            fma2(acc[2 * p + 0], av.x, wd);
            fma2(acc[2 * p + 1], av.y, wd);
        }
    }

    const float bc = bg[c];
    #pragma unroll
    for (int k = 0; k < 16; k++) {
        const float lo = __uint_as_float((unsigned)(acc[k] & 0xffffffffu));
        const float hi = __uint_as_float((unsigned)(acc[k] >> 32));
        const int r0 = i0 + 2 * k, r1 = r0 + 1;
        if (r0 < n) out[(size_t)r0 * ODIM + c] = fmaxf(lo + bc, 0.0f);
        if (r1 < n) out[(size_t)r1 * ODIM + c] = fmaxf(hi + bc, 0.0f);
    }
}

// ---------------------------------------------------------------------------
extern "C" void kernel_launch(void* const* d_in, const int* in_sizes, int n_in,
                              void* d_out, int out_size)
{
    const float* x   = (const float*)d_in[0];
    const float* pos = (const float*)d_in[1];
    // d_in[2] = batch (all zeros, unused)
    const float* W1  = (const float*)d_in[3];
    const float* b1  = (const float*)d_in[4];
    const float* W2  = (const float*)d_in[5];
    const float* b2  = (const float*)d_in[6];
    const float* Wg  = (const float*)d_in[7];
    const float* bg  = (const float*)d_in[8];
    float* out = (float*)d_out;

    const int n = in_sizes[2];

    int prep_work = H2DIM * ODIM + 64 * 32;
    if (n > prep_work) prep_work = n;
    prep_kernel<<<(prep_work + 255) / 256, 256>>>(W2, Wg, pos, n);
    scan_kernel<<<1, NCELLS>>>();
    scatter_kernel<<<(n + 255) / 256, 256>>>(n);
    knn_kernel<<<NCELLS, 128>>>();
    g_kernel<<<(n + 7) / 8, 128>>>(x, W1, b1, n);
    compute_kernel<<<n, 128>>>(pos, W1, b2, n);
    gemm_kernel<<<(n + 31) / 32, 256>>>(bg, out, n);
}

// round 15
// speedup vs baseline: 1.4582x; 1.4582x over previous
#include <cuda_runtime.h>
#include <cuda_bf16.h>
#include <cstdint>

#define NPTS   8192
#define KNBR   64
#define CIN    64
#define H1DIM  64
#define H2DIM  128
#define ODIM   256
#define R2     0.015625f   // 0.125^2 exactly
#define CAP    192         // per-target hit cap (mean ~60 in-radius)
#define GRID   8           // 8x8x8 cells, width 0.125 == R
#define NCELLS (GRID * GRID * GRID)

#define BSTRIDE 72         // halves per row of B planes (144B, 16B-aligned, conflict-free)

typedef unsigned long long ull;

// ---- scratch (device globals; no allocation allowed) ----------------------
__device__ int    g_nbr[NPTS * KNBR];
__device__ float  g_G  [NPTS * CIN];        // x @ W1[:64] + b1
__device__ float  g_AGG[NPTS * H2DIM];      // max-aggregated h2
__device__ float2 g_Wgd[H2DIM * ODIM];      // Wg duplicated (w,w)
__device__ float4 g_pos4[NPTS];             // (x, y, z, |p|^2)
__device__ uint4  g_AF4[64 * 32];           // pre-baked W2^T mma A-fragments
                                            // frag = ((w*2+mt)*4+kt)*2+plane, [frag][lane]
// spatial grid (cnt/fill zero at entry each call: zero-init at load, re-zeroed
// by scan_kernel after consuming -> graph-replay safe)
__device__ int    g_cell_cnt[NCELLS];
__device__ int    g_cell_start[NCELLS];
__device__ int    g_cell_end[NCELLS];
__device__ int    g_cell_fill[NCELLS];
__device__ float4 g_pos4s[NPTS];
__device__ int    g_ptid[NPTS];

__device__ __forceinline__ void fma2(ull& d, ull a, ull b) {
    asm("fma.rn.f32x2 %0, %1, %2, %0;" : "+l"(d) : "l"(a), "l"(b));
}
__device__ __forceinline__ int cell_of(float v) {
    int c = (int)(v * (float)GRID);
    return min(max(c, 0), GRID - 1);
}
// round-to-nearest-even fp32 -> bf16 (bits)  (prep-side; matches cvt.rn)
__device__ __forceinline__ unsigned bf16rn(float f) {
    unsigned u = __float_as_uint(f);
    return (u + 0x7FFFu + ((u >> 16) & 1u)) >> 16;
}
// hardware pack: bits[15:0] = bf16rn(a), bits[31:16] = bf16rn(b)
__device__ __forceinline__ uint32_t pack_bf16x2(float a, float b) {
    uint32_t r;
    asm("cvt.rn.bf16x2.f32 %0, %1, %2;" : "=r"(r) : "f"(b), "f"(a));
    return r;
}
__device__ __forceinline__ uint32_t smem_to_u32(const void* p) {
    uint32_t a;
    asm("{ .reg .u64 t; cvta.to.shared.u64 t, %1; cvt.u32.u64 %0, t; }" : "=r"(a) : "l"(p));
    return a;
}

// mma.sync m16n8k16 bf16, fp32 accum (baseline PTX; valid on compute_103)
#define MMA_BF16(acc, a, b0v, b1v) \
    asm volatile("mma.sync.aligned.m16n8k16.row.col.f32.bf16.bf16.f32 " \
        "{%0,%1,%2,%3}, {%4,%5,%6,%7}, {%8,%9}, {%0,%1,%2,%3};" \
        : "+f"((acc)[0]), "+f"((acc)[1]), "+f"((acc)[2]), "+f"((acc)[3]) \
        : "r"((a).x), "r"((a).y), "r"((a).z), "r"((a).w), "r"(b0v), "r"(b1v))

#define LDSM_X4(r0, r1, r2, r3, addr) \
    asm volatile("ldmatrix.sync.aligned.m8n8.x4.shared.b16 {%0,%1,%2,%3}, [%4];" \
        : "=r"(r0), "=r"(r1), "=r"(r2), "=r"(r3) : "r"(addr))

// ---------------------------------------------------------------------------
// Prep: Wg dup pairs; pos4 pack + cell histogram; bake W2^T A-fragments.
// ---------------------------------------------------------------------------
__global__ void prep_kernel(const float* __restrict__ W2, const float* __restrict__ Wg,
                            const float* __restrict__ pos, int n)
{
    int t = blockIdx.x * 256 + threadIdx.x;
    if (t < H2DIM * ODIM) {
        float w = Wg[t];
        g_Wgd[t] = make_float2(w, w);
    }
    if (t < n) {
        const float px = pos[3 * t + 0];
        const float py = pos[3 * t + 1];
        const float pz = pos[3 * t + 2];
        g_pos4[t] = make_float4(px, py, pz, px * px + py * py + pz * pz);
        const int c = (cell_of(pz) * GRID + cell_of(py)) * GRID + cell_of(px);
        atomicAdd(&g_cell_cnt[c], 1);      // cnt is zero at entry (see scan)
    }
    // A-fragment baking: a0=(r,k), a1=(r+8,k), a2=(r,k+8), a3=(r+8,k+8);
    // per-lane: row = base_m + lane/4, k = base_k + 2*(lane%4)+{0,1}
    int t4 = t - H2DIM * ODIM;
    if (t4 >= 0 && t4 < 64 * 32) {
        const int frag = t4 >> 5, lane = t4 & 31;
        const int plane = frag & 1;
        const int kt    = (frag >> 1) & 3;
        const int mt    = (frag >> 3) & 1;
        const int ww    = frag >> 4;
        const int r = 32 * ww + 16 * mt + (lane >> 2);
        const int k = 16 * kt + 2 * (lane & 3);
        uint32_t regs[4];
        #pragma unroll
        for (int j = 0; j < 4; j++) {
            const int rr = r + (j & 1) * 8;
            const int kk = k + (j >> 1) * 8;
            const float v0 = W2[(size_t)kk * H2DIM + rr];       // W2^T[rr][kk]
            const float v1 = W2[(size_t)(kk + 1) * H2DIM + rr];
            unsigned h0 = bf16rn(v0), h1 = bf16rn(v1);
            if (plane) {
                h0 = bf16rn(v0 - __uint_as_float(h0 << 16));
                h1 = bf16rn(v1 - __uint_as_float(h1 << 16));
            }
            regs[j] = h0 | (h1 << 16);
        }
        g_AF4[frag * 32 + lane] = make_uint4(regs[0], regs[1], regs[2], regs[3]);
    }
}

// ---------------------------------------------------------------------------
// Scan: counts -> start/end; then zero cnt/fill for the next replay.
// ---------------------------------------------------------------------------
__global__ void scan_kernel()
{
    __shared__ int buf[NCELLS];
    const int t = threadIdx.x;
    const int v = g_cell_cnt[t];
    buf[t] = v;
    __syncthreads();
    for (int o = 1; o < NCELLS; o <<= 1) {
        int u = (t >= o) ? buf[t - o] : 0;
        __syncthreads();
        buf[t] += u;
        __syncthreads();
    }
    g_cell_start[t] = buf[t] - v;   // exclusive prefix
    g_cell_end[t]   = buf[t];       // inclusive end
    g_cell_cnt[t]   = 0;            // reset for next graph replay
    g_cell_fill[t]  = 0;
}

__global__ void scatter_kernel(int n)
{
    int t = blockIdx.x * 256 + threadIdx.x;
    if (t >= n) return;
    const float4 p = g_pos4[t];
    const int c = (cell_of(p.z) * GRID + cell_of(p.y)) * GRID + cell_of(p.x);
    const int slot = g_cell_start[c] + atomicAdd(&g_cell_fill[c], 1);
    g_pos4s[slot] = p;
    g_ptid[slot]  = t;
}

// ---------------------------------------------------------------------------
// Grid KNN (reverted to warp-per-target; proven 30us shape) with warp-ballot
// slot compaction replacing smem atomics. 27-cell sweep covers all in-radius
// candidates (cell width == R); selection logic unchanged (radius filter,
// (d2,idx) rank if > K, pad with self).
// ---------------------------------------------------------------------------
__global__ void __launch_bounds__(128) knn_kernel(int n)
{
    __shared__ float cd2 [4][CAP];
    __shared__ int   cidx[4][CAP];

    const int w    = threadIdx.x >> 5;
    const int lane = threadIdx.x & 31;
    const int i    = blockIdx.x * 4 + w;
    if (i >= n) return;

    const float4 q = g_pos4[i];
    const int cx = cell_of(q.x), cy = cell_of(q.y), cz = cell_of(q.z);

    const int zlo = max(cz - 1, 0), zhi = min(cz + 1, GRID - 1);
    const int ylo = max(cy - 1, 0), yhi = min(cy + 1, GRID - 1);
    const int xlo = max(cx - 1, 0), xhi = min(cx + 1, GRID - 1);

    int cnt = 0;   // uniform across warp (ballot-carried)

    for (int z = zlo; z <= zhi; z++)
        for (int y = ylo; y <= yhi; y++) {
            const int c0 = (z * GRID + y) * GRID + xlo;
            const int c1 = (z * GRID + y) * GRID + xhi;
            const int s0 = g_cell_start[c0];
            const int s1 = g_cell_end[c1];
            for (int sb = s0; sb < s1; sb += 32) {     // uniform batches
                const int s = sb + lane;
                bool hit = false;
                float d2 = 0.0f;
                if (s < s1) {
                    const float4 p = g_pos4s[s];
                    const float dot = p.x * q.x + p.y * q.y + p.z * q.z;
                    d2 = (q.w + p.w) - 2.0f * dot;     // same formula as reference
                    hit = (d2 <= R2);
                }
                const unsigned m = __ballot_sync(0xffffffffu, hit);
                if (hit) {
                    const int sl = cnt + __popc(m & ((1u << lane) - 1u));
                    if (sl < CAP) { cd2[w][sl] = d2; cidx[w][sl] = g_ptid[s]; }
                }
                cnt += __popc(m);
            }
        }
    __syncwarp();

    int M = cnt; if (M > CAP) M = CAP;

    if (M <= KNBR) {
        for (int l = lane; l < KNBR; l += 32)
            g_nbr[i * KNBR + l] = (l < M) ? cidx[w][l] : i;   // pad with self
    } else {
        for (int m = lane; m < M; m += 32) {
            const float dm = cd2[w][m];
            const int   im = cidx[w][m];
            int rank = 0;
            for (int qq = 0; qq < M; qq++) {
                const float dq = cd2[w][qq];
                rank += (dq < dm) || (dq == dm && cidx[w][qq] < im);
            }
            if (rank < KNBR) g_nbr[i * KNBR + rank] = cidx[w][m];
        }
    }
}

// ---------------------------------------------------------------------------
// G precompute: G = x @ W1[0:64,:] + b1
// ---------------------------------------------------------------------------
__global__ void __launch_bounds__(128) g_kernel(
    const float* __restrict__ x, const float* __restrict__ W1,
    const float* __restrict__ b1, int n)
{
    __shared__ __align__(16) float xs[8 * 64];
    const int tid = threadIdx.x;
    const int i0  = blockIdx.x * 8;

    for (int idx = tid; idx < 512; idx += 128) {
        int p = idx >> 6, d = idx & 63;
        xs[idx] = (i0 + p < n) ? x[(size_t)(i0 + p) * 64 + d] : 0.0f;
    }
    __syncthreads();

    const int p  = tid >> 4;
    const int c4 = (tid & 15) * 4;
    if (i0 + p >= n) return;

    float4 acc = *(const float4*)&b1[c4];
    const float* xr = &xs[p * 64];
    #pragma unroll 8
    for (int d = 0; d < 64; d++) {
        const float xv = xr[d];
        float4 w = *(const float4*)&W1[d * 64 + c4];
        acc.x = fmaf(xv, w.x, acc.x);
        acc.y = fmaf(xv, w.y, acc.y);
        acc.z = fmaf(xv, w.z, acc.z);
        acc.w = fmaf(xv, w.w, acc.w);
    }
    *(float4*)&g_G[(size_t)(i0 + p) * 64 + c4] = acc;
}

// ---------------------------------------------------------------------------
// Main edge kernel: one block per point, 128 threads. (HMMA path unchanged;
// rel now computed from packed g_pos4 — identical float values.)
// ---------------------------------------------------------------------------
__global__ void __launch_bounds__(128) compute_kernel(
    const float* __restrict__ W1, const float* __restrict__ b2, int n)
{
    __shared__ __align__(16) unsigned short BHIs[KNBR * BSTRIDE];
    __shared__ __align__(16) unsigned short BLOs[KNBR * BSTRIDE];
    __shared__ int   nbr_s[KNBR];
    __shared__ float relx[KNBR], rely[KNBR], relz[KNBR];
    __shared__ float red[H2DIM];

    const int i    = blockIdx.x;
    const int tid  = threadIdx.x;
    const int wid  = tid >> 5;
    const int lane = tid & 31;
    if (i >= n) return;

    if (tid < KNBR) {
        const int j = g_nbr[i * KNBR + tid];
        nbr_s[tid] = j;
        const float4 pj = g_pos4[j];
        const float4 pi = g_pos4[i];
        relx[tid] = pj.x - pi.x;
        rely[tid] = pj.y - pi.y;
        relz[tid] = pj.z - pi.z;
    }
    __syncthreads();

    // ---- Phase A: fp32 h1 -> bf16 hi/lo planes, [nbr][d] stride 72 halves ----
    {
        const int nk0 = tid & 7;
        const int c4  = (tid >> 3) * 4;

        float4 g4[8];
        #pragma unroll
        for (int it = 0; it < 8; it++)
            g4[it] = *(const float4*)&g_G[(size_t)nbr_s[nk0 + it * 8] * 64 + c4];

        const float4 wx = *(const float4*)&W1[64 * 64 + c4];
        const float4 wy = *(const float4*)&W1[65 * 64 + c4];
        const float4 wz = *(const float4*)&W1[66 * 64 + c4];

        #pragma unroll
        for (int it = 0; it < 8; it++) {
            const int nk = nk0 + it * 8;
            const float rx = relx[nk], ry = rely[nk], rz = relz[nk];
            float h0 = fmaxf(fmaf(rx, wx.x, fmaf(ry, wy.x, fmaf(rz, wz.x, g4[it].x))), 0.0f);
            float h1 = fmaxf(fmaf(rx, wx.y, fmaf(ry, wy.y, fmaf(rz, wz.y, g4[it].y))), 0.0f);
            float h2 = fmaxf(fmaf(rx, wx.z, fmaf(ry, wy.z, fmaf(rz, wz.z, g4[it].z))), 0.0f);
            float h3 = fmaxf(fmaf(rx, wx.w, fmaf(ry, wy.w, fmaf(rz, wz.w, g4[it].w))), 0.0f);

            const uint32_t p01 = pack_bf16x2(h0, h1);
            const uint32_t p23 = pack_bf16x2(h2, h3);
            const float f0 = __uint_as_float(p01 << 16);
            const float f1 = __uint_as_float(p01 & 0xFFFF0000u);
            const float f2 = __uint_as_float(p23 << 16);
            const float f3 = __uint_as_float(p23 & 0xFFFF0000u);
            const uint32_t q01 = pack_bf16x2(h0 - f0, h1 - f1);
            const uint32_t q23 = pack_bf16x2(h2 - f2, h3 - f3);

            const ull hiw = (ull)p01 | ((ull)p23 << 32);
            const ull low = (ull)q01 | ((ull)q23 << 32);
            *(ull*)&BHIs[nk * BSTRIDE + c4] = hiw;
            *(ull*)&BLOs[nk * BSTRIDE + c4] = low;
        }
    }
    __syncthreads();

    // ---- Phase B: mma.sync layer 2 + max-agg ----
    {
        const uint32_t bhi_base = smem_to_u32(BHIs);
        const uint32_t blo_base = smem_to_u32(BLOs);
        const int g  = lane >> 3;      // ldmatrix lane group 0..3
        const int gr = lane & 7;

        float mx[2][2] = {{-1e30f, -1e30f}, {-1e30f, -1e30f}};   // [mt][rowhalf]

        #pragma unroll
        for (int nh = 0; nh < 2; nh++) {
            float acc[2][4][4];
            #pragma unroll
            for (int mt = 0; mt < 2; mt++)
                #pragma unroll
                for (int nt = 0; nt < 4; nt++)
                    #pragma unroll
                    for (int e = 0; e < 4; e++) acc[mt][nt][e] = 0.0f;

            #pragma unroll
            for (int kt = 0; kt < 4; kt++) {
                // A fragments (pre-baked, coalesced LDG.128, L1-hot)
                uint4 ah[2], al[2];
                ah[0] = g_AF4[(((wid * 2 + 0) * 4 + kt) * 2 + 0) * 32 + lane];
                ah[1] = g_AF4[(((wid * 2 + 1) * 4 + kt) * 2 + 0) * 32 + lane];
                al[0] = g_AF4[(((wid * 2 + 0) * 4 + kt) * 2 + 1) * 32 + lane];
                al[1] = g_AF4[(((wid * 2 + 1) * 4 + kt) * 2 + 1) * 32 + lane];

                // B fragments via plain ldmatrix.x4
                uint32_t bh[4][2], bl[4][2];
                #pragma unroll
                for (int ntp = 0; ntp < 2; ntp++) {
                    const int row = nh * 32 + ntp * 16 + (g >> 1) * 8 + gr;
                    const uint32_t off = (uint32_t)(row * (BSTRIDE * 2) + (kt * 16 + (g & 1) * 8) * 2);
                    uint32_t r0, r1, r2, r3;
                    LDSM_X4(r0, r1, r2, r3, bhi_base + off);
                    bh[2 * ntp][0] = r0; bh[2 * ntp][1] = r1;
                    bh[2 * ntp + 1][0] = r2; bh[2 * ntp + 1][1] = r3;
                    LDSM_X4(r0, r1, r2, r3, blo_base + off);
                    bl[2 * ntp][0] = r0; bl[2 * ntp][1] = r1;
                    bl[2 * ntp + 1][0] = r2; bl[2 * ntp + 1][1] = r3;
                }

                #pragma unroll
                for (int mt = 0; mt < 2; mt++)
                    #pragma unroll
                    for (int nt = 0; nt < 4; nt++) {
                        MMA_BF16(acc[mt][nt], ah[mt], bh[nt][0], bh[nt][1]);
                        MMA_BF16(acc[mt][nt], ah[mt], bl[nt][0], bl[nt][1]);
                        MMA_BF16(acc[mt][nt], al[mt], bh[nt][0], bh[nt][1]);
                    }
            }

            // fold this n-half into running maxes
            #pragma unroll
            for (int mt = 0; mt < 2; mt++)
                #pragma unroll
                for (int nt = 0; nt < 4; nt++) {
                    mx[mt][0] = fmaxf(mx[mt][0], fmaxf(acc[mt][nt][0], acc[mt][nt][1]));
                    mx[mt][1] = fmaxf(mx[mt][1], fmaxf(acc[mt][nt][2], acc[mt][nt][3]));
                }
        }

        // quad reduction: lanes sharing l/4 hold the same rows
        #pragma unroll
        for (int mt = 0; mt < 2; mt++)
            #pragma unroll
            for (int h = 0; h < 2; h++) {
                float v = mx[mt][h];
                v = fmaxf(v, __shfl_xor_sync(0xffffffffu, v, 1));
                v = fmaxf(v, __shfl_xor_sync(0xffffffffu, v, 2));
                mx[mt][h] = v;
            }
        if ((lane & 3) == 0) {
            const int q = lane >> 2;
            red[32 * wid + q]      = mx[0][0];
            red[32 * wid + 8 + q]  = mx[0][1];
            red[32 * wid + 16 + q] = mx[1][0];
            red[32 * wid + 24 + q] = mx[1][1];
        }
    }
    __syncthreads();

    // relu(max + b2) == max relu(z + b2)  (max monotone)
    g_AGG[(size_t)i * H2DIM + tid] = fmaxf(red[tid] + b2[tid], 0.0f);
}

// ---------------------------------------------------------------------------
// Global layer GEMM: out = relu(AGG @ Wg + bg), packed f32x2.
// ---------------------------------------------------------------------------
__global__ void __launch_bounds__(256) gemm_kernel(
    const float* __restrict__ bg, float* __restrict__ out, int n)
{
    __shared__ __align__(16) float As[H2DIM * 36];
    const int tid = threadIdx.x;
    const int i0  = blockIdx.x * 32;

    for (int idx = tid; idx < 32 * H2DIM; idx += 256) {
        const int r = idx >> 7, d = idx & 127;
        const int row = (i0 + r < n) ? (i0 + r) : (n - 1);
        As[d * 36 + r] = g_AGG[(size_t)row * H2DIM + d];
    }
    __syncthreads();

    const int c = tid;
    ull acc[16];
    #pragma unroll
    for (int p = 0; p < 16; p++) acc[p] = 0ull;

    const ull* wp = reinterpret_cast<const ull*>(g_Wgd) + c;
    #pragma unroll 2
    for (int d = 0; d < H2DIM; d++) {
        const ull wd = *wp; wp += ODIM;
        const float* ar = &As[d * 36];
        #pragma unroll
        for (int p = 0; p < 8; p++) {
            const ulonglong2 av = *reinterpret_cast<const ulonglong2*>(ar + 4 * p);
            fma2(acc[2 * p + 0], av.x, wd);
            fma2(acc[2 * p + 1], av.y, wd);
        }
    }

    const float bc = bg[c];
    #pragma unroll
    for (int k = 0; k < 16; k++) {
        const float lo = __uint_as_float((unsigned)(acc[k] & 0xffffffffu));
        const float hi = __uint_as_float((unsigned)(acc[k] >> 32));
        const int r0 = i0 + 2 * k, r1 = r0 + 1;
        if (r0 < n) out[(size_t)r0 * ODIM + c] = fmaxf(lo + bc, 0.0f);
        if (r1 < n) out[(size_t)r1 * ODIM + c] = fmaxf(hi + bc, 0.0f);
    }
}

// ---------------------------------------------------------------------------
extern "C" void kernel_launch(void* const* d_in, const int* in_sizes, int n_in,
                              void* d_out, int out_size)
{
    const float* x   = (const float*)d_in[0];
    const float* pos = (const float*)d_in[1];
    // d_in[2] = batch (all zeros, unused)
    const float* W1  = (const float*)d_in[3];
    const float* b1  = (const float*)d_in[4];
    const float* W2  = (const float*)d_in[5];
    const float* b2  = (const float*)d_in[6];
    const float* Wg  = (const float*)d_in[7];
    const float* bg  = (const float*)d_in[8];
    float* out = (float*)d_out;

    const int n = in_sizes[2];

    int prep_work = H2DIM * ODIM + 64 * 32;
    if (n > prep_work) prep_work = n;
    prep_kernel<<<(prep_work + 255) / 256, 256>>>(W2, Wg, pos, n);
    scan_kernel<<<1, NCELLS>>>();
    scatter_kernel<<<(n + 255) / 256, 256>>>(n);
    knn_kernel<<<(n + 3) / 4, 128>>>(n);
    g_kernel<<<(n + 7) / 8, 128>>>(x, W1, b1, n);
    compute_kernel<<<n, 128>>>(W1, b2, n);
    gemm_kernel<<<(n + 31) / 32, 256>>>(bg, out, n);
}

// round 16
// speedup vs baseline: 1.6095x; 1.1038x over previous
#include <cuda_runtime.h>
#include <cuda_bf16.h>
#include <cstdint>

#define NPTS   8192
#define KNBR   64
#define CIN    64
#define H1DIM  64
#define H2DIM  128
#define ODIM   256
#define R2     0.015625f   // 0.125^2 exactly
#define CAP    192         // per-target hit cap (mean ~60 in-radius)
#define GRID   8           // 8x8x8 cells, width 0.125 == R
#define NCELLS (GRID * GRID * GRID)

#define BSTRIDE 72         // halves per row of B planes (144B, 16B-aligned, conflict-free)

typedef unsigned long long ull;

// ---- scratch (device globals; no allocation allowed) ----------------------
__device__ int    g_nbr[NPTS * KNBR];
__device__ float  g_G  [NPTS * CIN];        // x @ W1[:64] + b1
__device__ float  g_AGG[NPTS * H2DIM];      // max-aggregated h2
__device__ float2 g_Wgd[H2DIM * ODIM];      // Wg duplicated (w,w)
__device__ float4 g_pos4[NPTS];             // (x, y, z, |p|^2)
__device__ int    g_rank[NPTS];             // within-cell rank (from prep's atomic)
__device__ uint4  g_AF4[64 * 32];           // pre-baked W2^T mma A-fragments
                                            // frag = ((w*2+mt)*4+kt)*2+plane, [frag][lane]
// spatial grid (cnt zero at entry each call: zero-init at load, re-zeroed by
// scan_kernel after consuming -> graph-replay safe)
__device__ int    g_cell_cnt[NCELLS];
__device__ int    g_cell_start[NCELLS];
__device__ int    g_cell_end[NCELLS];
__device__ float4 g_pos4s[NPTS];
__device__ int    g_ptid[NPTS];

__device__ __forceinline__ void fma2(ull& d, ull a, ull b) {
    asm("fma.rn.f32x2 %0, %1, %2, %0;" : "+l"(d) : "l"(a), "l"(b));
}
__device__ __forceinline__ int cell_of(float v) {
    int c = (int)(v * (float)GRID);
    return min(max(c, 0), GRID - 1);
}
// round-to-nearest-even fp32 -> bf16 (bits)  (prep-side; matches cvt.rn)
__device__ __forceinline__ unsigned bf16rn(float f) {
    unsigned u = __float_as_uint(f);
    return (u + 0x7FFFu + ((u >> 16) & 1u)) >> 16;
}
// hardware pack: bits[15:0] = bf16rn(a), bits[31:16] = bf16rn(b)
__device__ __forceinline__ uint32_t pack_bf16x2(float a, float b) {
    uint32_t r;
    asm("cvt.rn.bf16x2.f32 %0, %1, %2;" : "=r"(r) : "f"(b), "f"(a));
    return r;
}
__device__ __forceinline__ uint32_t smem_to_u32(const void* p) {
    uint32_t a;
    asm("{ .reg .u64 t; cvta.to.shared.u64 t, %1; cvt.u32.u64 %0, t; }" : "=r"(a) : "l"(p));
    return a;
}

// mma.sync m16n8k16 bf16, fp32 accum (baseline PTX; valid on compute_103)
#define MMA_BF16(acc, a, b0v, b1v) \
    asm volatile("mma.sync.aligned.m16n8k16.row.col.f32.bf16.bf16.f32 " \
        "{%0,%1,%2,%3}, {%4,%5,%6,%7}, {%8,%9}, {%0,%1,%2,%3};" \
        : "+f"((acc)[0]), "+f"((acc)[1]), "+f"((acc)[2]), "+f"((acc)[3]) \
        : "r"((a).x), "r"((a).y), "r"((a).z), "r"((a).w), "r"(b0v), "r"(b1v))

#define LDSM_X4(r0, r1, r2, r3, addr) \
    asm volatile("ldmatrix.sync.aligned.m8n8.x4.shared.b16 {%0,%1,%2,%3}, [%4];" \
        : "=r"(r0), "=r"(r1), "=r"(r2), "=r"(r3) : "r"(addr))

// ---------------------------------------------------------------------------
// Prep: Wg dup pairs; pos4 pack + cell histogram (rank captured); bake W2^T
// A-fragments.
// ---------------------------------------------------------------------------
__global__ void prep_kernel(const float* __restrict__ W2, const float* __restrict__ Wg,
                            const float* __restrict__ pos, int n)
{
    int t = blockIdx.x * 256 + threadIdx.x;
    if (t < H2DIM * ODIM) {
        float w = Wg[t];
        g_Wgd[t] = make_float2(w, w);
    }
    if (t < n) {
        const float px = pos[3 * t + 0];
        const float py = pos[3 * t + 1];
        const float pz = pos[3 * t + 2];
        g_pos4[t] = make_float4(px, py, pz, px * px + py * py + pz * pz);
        const int c = (cell_of(pz) * GRID + cell_of(py)) * GRID + cell_of(px);
        g_rank[t] = atomicAdd(&g_cell_cnt[c], 1);   // cnt zero at entry (see scan)
    }
    // A-fragment baking
    int t4 = t - H2DIM * ODIM;
    if (t4 >= 0 && t4 < 64 * 32) {
        const int frag = t4 >> 5, lane = t4 & 31;
        const int plane = frag & 1;
        const int kt    = (frag >> 1) & 3;
        const int mt    = (frag >> 3) & 1;
        const int ww    = frag >> 4;
        const int r = 32 * ww + 16 * mt + (lane >> 2);
        const int k = 16 * kt + 2 * (lane & 3);
        uint32_t regs[4];
        #pragma unroll
        for (int j = 0; j < 4; j++) {
            const int rr = r + (j & 1) * 8;
            const int kk = k + (j >> 1) * 8;
            const float v0 = W2[(size_t)kk * H2DIM + rr];       // W2^T[rr][kk]
            const float v1 = W2[(size_t)(kk + 1) * H2DIM + rr];
            unsigned h0 = bf16rn(v0), h1 = bf16rn(v1);
            if (plane) {
                h0 = bf16rn(v0 - __uint_as_float(h0 << 16));
                h1 = bf16rn(v1 - __uint_as_float(h1 << 16));
            }
            regs[j] = h0 | (h1 << 16);
        }
        g_AF4[frag * 32 + lane] = make_uint4(regs[0], regs[1], regs[2], regs[3]);
    }
}

// ---------------------------------------------------------------------------
// Scan: counts -> start/end; then zero cnt for the next replay.
// ---------------------------------------------------------------------------
__global__ void scan_kernel()
{
    __shared__ int buf[NCELLS];
    const int t = threadIdx.x;
    const int v = g_cell_cnt[t];
    buf[t] = v;
    __syncthreads();
    for (int o = 1; o < NCELLS; o <<= 1) {
        int u = (t >= o) ? buf[t - o] : 0;
        __syncthreads();
        buf[t] += u;
        __syncthreads();
    }
    g_cell_start[t] = buf[t] - v;   // exclusive prefix
    g_cell_end[t]   = buf[t];       // inclusive end
    g_cell_cnt[t]   = 0;            // reset for next graph replay
}

// ---------------------------------------------------------------------------
// Fused G-precompute + scatter. Blocks [0, nG) compute G = x@W1[:64]+b1
// (8 points per block); blocks [nG, nG+nS) scatter points to sorted order
// (atomic-free: slot = cell_start + rank captured in prep).
// ---------------------------------------------------------------------------
__global__ void __launch_bounds__(128) gs_kernel(
    const float* __restrict__ x, const float* __restrict__ W1,
    const float* __restrict__ b1, int n)
{
    const int nG = (n + 7) / 8;
    const int tid = threadIdx.x;

    if ((int)blockIdx.x >= nG) {
        const int t = ((int)blockIdx.x - nG) * 128 + tid;
        if (t < n) {
            const float4 p = g_pos4[t];
            const int c = (cell_of(p.z) * GRID + cell_of(p.y)) * GRID + cell_of(p.x);
            const int slot = g_cell_start[c] + g_rank[t];
            g_pos4s[slot] = p;
            g_ptid[slot]  = t;
        }
        return;
    }

    __shared__ __align__(16) float xs[8 * 64];
    const int i0 = blockIdx.x * 8;

    for (int idx = tid; idx < 512; idx += 128) {
        int p = idx >> 6, d = idx & 63;
        xs[idx] = (i0 + p < n) ? x[(size_t)(i0 + p) * 64 + d] : 0.0f;
    }
    __syncthreads();

    const int p  = tid >> 4;
    const int c4 = (tid & 15) * 4;
    if (i0 + p >= n) return;

    float4 acc = *(const float4*)&b1[c4];
    const float* xr = &xs[p * 64];
    #pragma unroll 8
    for (int d = 0; d < 64; d++) {
        const float xv = xr[d];
        float4 w = *(const float4*)&W1[d * 64 + c4];
        acc.x = fmaf(xv, w.x, acc.x);
        acc.y = fmaf(xv, w.y, acc.y);
        acc.z = fmaf(xv, w.z, acc.z);
        acc.w = fmaf(xv, w.w, acc.w);
    }
    *(float4*)&g_G[(size_t)(i0 + p) * 64 + c4] = acc;
}

// ---------------------------------------------------------------------------
// Grid KNN, warp-per-target, with exact ball-cell pruning: rows whose box
// distance exceeds R are skipped, and the x-cell range is trimmed to cells
// intersecting the R-ball (thresholds padded >=5x beyond the worst-case
// float error of the d2 formula, so no float-d2 <= R2 candidate is dropped).
// Selection on sortable u64 keys (d2bits<<32 | idx) == (d2, idx) lex order.
// ---------------------------------------------------------------------------
__global__ void __launch_bounds__(128) knn_kernel(int n)
{
    __shared__ ull ckey[4][CAP];

    const int w    = threadIdx.x >> 5;
    const int lane = threadIdx.x & 31;
    const int i    = blockIdx.x * 4 + w;
    if (i >= n) return;

    const float4 q = g_pos4[i];
    const int cx = cell_of(q.x), cy = cell_of(q.y), cz = cell_of(q.z);

    const int zlo = max(cz - 1, 0), zhi = min(cz + 1, GRID - 1);
    const int ylo = max(cy - 1, 0), yhi = min(cy + 1, GRID - 1);
    const int xlo = max(cx - 1, 0), xhi = min(cx + 1, GRID - 1);

    const float H = 0.125f;
    int cnt = 0;   // uniform across warp (ballot-carried)

    for (int z = zlo; z <= zhi; z++) {
        const float dz  = fmaxf(fmaxf((float)z * H - q.z, q.z - (float)(z + 1) * H), 0.0f);
        const float dz2 = dz * dz;
        for (int y = ylo; y <= yhi; y++) {
            const float dy   = fmaxf(fmaxf((float)y * H - q.y, q.y - (float)(y + 1) * H), 0.0f);
            const float dyz2 = dz2 + dy * dy;
            if (dyz2 > R2 + 4e-6f) continue;                    // row fully outside ball
            const float dxa = sqrtf(fmaxf(R2 + 4e-6f - dyz2, 0.0f)) + 4e-5f;
            const int xl = max(xlo, cell_of(q.x - dxa));
            const int xh = min(xhi, cell_of(q.x + dxa));
            if (xl > xh) continue;

            const int base = (z * GRID + y) * GRID;
            const int s0 = g_cell_start[base + xl];
            const int s1 = g_cell_end[base + xh];
            for (int sb = s0; sb < s1; sb += 32) {              // uniform batches
                const int s = sb + lane;
                bool hit = false;
                float d2 = 0.0f;
                if (s < s1) {
                    const float4 p = g_pos4s[s];
                    const float dot = p.x * q.x + p.y * q.y + p.z * q.z;
                    d2 = (q.w + p.w) - 2.0f * dot;              // same formula as reference
                    hit = (d2 <= R2);
                }
                const unsigned m = __ballot_sync(0xffffffffu, hit);
                if (hit) {
                    const int sl = cnt + __popc(m & ((1u << lane) - 1u));
                    if (sl < CAP) {
                        // clamp only the KEY (self can round slightly negative;
                        // still strictly smallest, matching reference top_k)
                        const unsigned kb = __float_as_uint(fmaxf(d2, 0.0f));
                        ckey[w][sl] = ((ull)kb << 32) | (unsigned)g_ptid[s];
                    }
                }
                cnt += __popc(m);
            }
        }
    }
    __syncwarp();

    int M = cnt; if (M > CAP) M = CAP;

    if (M <= KNBR) {
        for (int l = lane; l < KNBR; l += 32)
            g_nbr[i * KNBR + l] = (l < M) ? (int)(unsigned)(ckey[w][l] & 0xffffffffu) : i;
    } else {
        for (int m = lane; m < M; m += 32) {
            const ull km = ckey[w][m];
            int rank = 0;
            for (int qq = 0; qq < M; qq++)
                rank += (ckey[w][qq] < km);     // unique keys (idx in low bits)
            if (rank < KNBR) g_nbr[i * KNBR + rank] = (int)(unsigned)(km & 0xffffffffu);
        }
    }
}

// ---------------------------------------------------------------------------
// Main edge kernel: one block per point, 128 threads. (HMMA path unchanged.)
// ---------------------------------------------------------------------------
__global__ void __launch_bounds__(128) compute_kernel(
    const float* __restrict__ W1, const float* __restrict__ b2, int n)
{
    __shared__ __align__(16) unsigned short BHIs[KNBR * BSTRIDE];
    __shared__ __align__(16) unsigned short BLOs[KNBR * BSTRIDE];
    __shared__ int   nbr_s[KNBR];
    __shared__ float relx[KNBR], rely[KNBR], relz[KNBR];
    __shared__ float red[H2DIM];

    const int i    = blockIdx.x;
    const int tid  = threadIdx.x;
    const int wid  = tid >> 5;
    const int lane = tid & 31;
    if (i >= n) return;

    if (tid < KNBR) {
        const int j = g_nbr[i * KNBR + tid];
        nbr_s[tid] = j;
        const float4 pj = g_pos4[j];
        const float4 pi = g_pos4[i];
        relx[tid] = pj.x - pi.x;
        rely[tid] = pj.y - pi.y;
        relz[tid] = pj.z - pi.z;
    }
    __syncthreads();

    // ---- Phase A: fp32 h1 -> bf16 hi/lo planes, [nbr][d] stride 72 halves ----
    {
        const int nk0 = tid & 7;
        const int c4  = (tid >> 3) * 4;

        float4 g4[8];
        #pragma unroll
        for (int it = 0; it < 8; it++)
            g4[it] = *(const float4*)&g_G[(size_t)nbr_s[nk0 + it * 8] * 64 + c4];

        const float4 wx = *(const float4*)&W1[64 * 64 + c4];
        const float4 wy = *(const float4*)&W1[65 * 64 + c4];
        const float4 wz = *(const float4*)&W1[66 * 64 + c4];

        #pragma unroll
        for (int it = 0; it < 8; it++) {
            const int nk = nk0 + it * 8;
            const float rx = relx[nk], ry = rely[nk], rz = relz[nk];
            float h0 = fmaxf(fmaf(rx, wx.x, fmaf(ry, wy.x, fmaf(rz, wz.x, g4[it].x))), 0.0f);
            float h1 = fmaxf(fmaf(rx, wx.y, fmaf(ry, wy.y, fmaf(rz, wz.y, g4[it].y))), 0.0f);
            float h2 = fmaxf(fmaf(rx, wx.z, fmaf(ry, wy.z, fmaf(rz, wz.z, g4[it].z))), 0.0f);
            float h3 = fmaxf(fmaf(rx, wx.w, fmaf(ry, wy.w, fmaf(rz, wz.w, g4[it].w))), 0.0f);

            const uint32_t p01 = pack_bf16x2(h0, h1);
            const uint32_t p23 = pack_bf16x2(h2, h3);
            const float f0 = __uint_as_float(p01 << 16);
            const float f1 = __uint_as_float(p01 & 0xFFFF0000u);
            const float f2 = __uint_as_float(p23 << 16);
            const float f3 = __uint_as_float(p23 & 0xFFFF0000u);
            const uint32_t q01 = pack_bf16x2(h0 - f0, h1 - f1);
            const uint32_t q23 = pack_bf16x2(h2 - f2, h3 - f3);

            const ull hiw = (ull)p01 | ((ull)p23 << 32);
            const ull low = (ull)q01 | ((ull)q23 << 32);
            *(ull*)&BHIs[nk * BSTRIDE + c4] = hiw;
            *(ull*)&BLOs[nk * BSTRIDE + c4] = low;
        }
    }
    __syncthreads();

    // ---- Phase B: mma.sync layer 2 + max-agg ----
    {
        const uint32_t bhi_base = smem_to_u32(BHIs);
        const uint32_t blo_base = smem_to_u32(BLOs);
        const int g  = lane >> 3;      // ldmatrix lane group 0..3
        const int gr = lane & 7;

        float mx[2][2] = {{-1e30f, -1e30f}, {-1e30f, -1e30f}};   // [mt][rowhalf]

        #pragma unroll
        for (int nh = 0; nh < 2; nh++) {
            float acc[2][4][4];
            #pragma unroll
            for (int mt = 0; mt < 2; mt++)
                #pragma unroll
                for (int nt = 0; nt < 4; nt++)
                    #pragma unroll
                    for (int e = 0; e < 4; e++) acc[mt][nt][e] = 0.0f;

            #pragma unroll
            for (int kt = 0; kt < 4; kt++) {
                // A fragments (pre-baked, coalesced LDG.128, L1-hot)
                uint4 ah[2], al[2];
                ah[0] = g_AF4[(((wid * 2 + 0) * 4 + kt) * 2 + 0) * 32 + lane];
                ah[1] = g_AF4[(((wid * 2 + 1) * 4 + kt) * 2 + 0) * 32 + lane];
                al[0] = g_AF4[(((wid * 2 + 0) * 4 + kt) * 2 + 1) * 32 + lane];
                al[1] = g_AF4[(((wid * 2 + 1) * 4 + kt) * 2 + 1) * 32 + lane];

                // B fragments via plain ldmatrix.x4
                uint32_t bh[4][2], bl[4][2];
                #pragma unroll
                for (int ntp = 0; ntp < 2; ntp++) {
                    const int row = nh * 32 + ntp * 16 + (g >> 1) * 8 + gr;
                    const uint32_t off = (uint32_t)(row * (BSTRIDE * 2) + (kt * 16 + (g & 1) * 8) * 2);
                    uint32_t r0, r1, r2, r3;
                    LDSM_X4(r0, r1, r2, r3, bhi_base + off);
                    bh[2 * ntp][0] = r0; bh[2 * ntp][1] = r1;
                    bh[2 * ntp + 1][0] = r2; bh[2 * ntp + 1][1] = r3;
                    LDSM_X4(r0, r1, r2, r3, blo_base + off);
                    bl[2 * ntp][0] = r0; bl[2 * ntp][1] = r1;
                    bl[2 * ntp + 1][0] = r2; bl[2 * ntp + 1][1] = r3;
                }

                #pragma unroll
                for (int mt = 0; mt < 2; mt++)
                    #pragma unroll
                    for (int nt = 0; nt < 4; nt++) {
                        MMA_BF16(acc[mt][nt], ah[mt], bh[nt][0], bh[nt][1]);
                        MMA_BF16(acc[mt][nt], ah[mt], bl[nt][0], bl[nt][1]);
                        MMA_BF16(acc[mt][nt], al[mt], bh[nt][0], bh[nt][1]);
                    }
            }

            // fold this n-half into running maxes
            #pragma unroll
            for (int mt = 0; mt < 2; mt++)
                #pragma unroll
                for (int nt = 0; nt < 4; nt++) {
                    mx[mt][0] = fmaxf(mx[mt][0], fmaxf(acc[mt][nt][0], acc[mt][nt][1]));
                    mx[mt][1] = fmaxf(mx[mt][1], fmaxf(acc[mt][nt][2], acc[mt][nt][3]));
                }
        }

        // quad reduction: lanes sharing l/4 hold the same rows
        #pragma unroll
        for (int mt = 0; mt < 2; mt++)
            #pragma unroll
            for (int h = 0; h < 2; h++) {
                float v = mx[mt][h];
                v = fmaxf(v, __shfl_xor_sync(0xffffffffu, v, 1));
                v = fmaxf(v, __shfl_xor_sync(0xffffffffu, v, 2));
                mx[mt][h] = v;
            }
        if ((lane & 3) == 0) {
            const int q = lane >> 2;
            red[32 * wid + q]      = mx[0][0];
            red[32 * wid + 8 + q]  = mx[0][1];
            red[32 * wid + 16 + q] = mx[1][0];
            red[32 * wid + 24 + q] = mx[1][1];
        }
    }
    __syncthreads();

    // relu(max + b2) == max relu(z + b2)  (max monotone)
    g_AGG[(size_t)i * H2DIM + tid] = fmaxf(red[tid] + b2[tid], 0.0f);
}

// ---------------------------------------------------------------------------
// Global layer GEMM: out = relu(AGG @ Wg + bg), packed f32x2.
// ---------------------------------------------------------------------------
__global__ void __launch_bounds__(256) gemm_kernel(
    const float* __restrict__ bg, float* __restrict__ out, int n)
{
    __shared__ __align__(16) float As[H2DIM * 36];
    const int tid = threadIdx.x;
    const int i0  = blockIdx.x * 32;

    for (int idx = tid; idx < 32 * H2DIM; idx += 256) {
        const int r = idx >> 7, d = idx & 127;
        const int row = (i0 + r < n) ? (i0 + r) : (n - 1);
        As[d * 36 + r] = g_AGG[(size_t)row * H2DIM + d];
    }
    __syncthreads();

    const int c = tid;
    ull acc[16];
    #pragma unroll
    for (int p = 0; p < 16; p++) acc[p] = 0ull;

    const ull* wp = reinterpret_cast<const ull*>(g_Wgd) + c;
    #pragma unroll 2
    for (int d = 0; d < H2DIM; d++) {
        const ull wd = *wp; wp += ODIM;
        const float* ar = &As[d * 36];
        #pragma unroll
        for (int p = 0; p < 8; p++) {
            const ulonglong2 av = *reinterpret_cast<const ulonglong2*>(ar + 4 * p);
            fma2(acc[2 * p + 0], av.x, wd);
            fma2(acc[2 * p + 1], av.y, wd);
        }
    }

    const float bc = bg[c];
    #pragma unroll
    for (int k = 0; k < 16; k++) {
        const float lo = __uint_as_float((unsigned)(acc[k] & 0xffffffffu));
        const float hi = __uint_as_float((unsigned)(acc[k] >> 32));
        const int r0 = i0 + 2 * k, r1 = r0 + 1;
        if (r0 < n) out[(size_t)r0 * ODIM + c] = fmaxf(lo + bc, 0.0f);
        if (r1 < n) out[(size_t)r1 * ODIM + c] = fmaxf(hi + bc, 0.0f);
    }
}

// ---------------------------------------------------------------------------
extern "C" void kernel_launch(void* const* d_in, const int* in_sizes, int n_in,
                              void* d_out, int out_size)
{
    const float* x   = (const float*)d_in[0];
    const float* pos = (const float*)d_in[1];
    // d_in[2] = batch (all zeros, unused)
    const float* W1  = (const float*)d_in[3];
    const float* b1  = (const float*)d_in[4];
    const float* W2  = (const float*)d_in[5];
    const float* b2  = (const float*)d_in[6];
    const float* Wg  = (const float*)d_in[7];
    const float* bg  = (const float*)d_in[8];
    float* out = (float*)d_out;

    const int n = in_sizes[2];

    int prep_work = H2DIM * ODIM + 64 * 32;
    if (n > prep_work) prep_work = n;
    prep_kernel<<<(prep_work + 255) / 256, 256>>>(W2, Wg, pos, n);
    scan_kernel<<<1, NCELLS>>>();
    gs_kernel<<<(n + 7) / 8 + (n + 127) / 128, 128>>>(x, W1, b1, n);
    knn_kernel<<<(n + 3) / 4, 128>>>(n);
    compute_kernel<<<n, 128>>>(W1, b2, n);
    gemm_kernel<<<(n + 31) / 32, 256>>>(bg, out, n);
}